// round 1
// baseline (speedup 1.0000x reference)
#include <cuda_runtime.h>

#define NN 100000
#define EE 1600000
#define NB 98   /* ceil(NN/1024) */

// ---------------- device scratch (no allocations allowed) ----------------
__device__ int   d_counts[NN];     // in-degree (w/o self loop)
__device__ int   d_offs[NN];       // CSR-T row starts
__device__ int   d_cursor[NN];     // fill cursors
__device__ int   d_bsums[NB];      // scan block sums
__device__ int   d_srcs[EE];       // CSR-T column indices (src per incoming edge)
__device__ float d_dinv[NN];       // rsqrt(deg)
__device__ float d_g1[NN * 64];    // dinv * (x @ W1)
__device__ float d_h1[NN * 64];    // relu(agg1 + b1)
__device__ float d_g2[NN * 32];    // dinv * (h1 @ W2)

// ---------------- CSR build ----------------
__global__ void zero_counts_kernel() {
    int i = blockIdx.x * blockDim.x + threadIdx.x;
    if (i < NN) d_counts[i] = 0;
}

__global__ void hist_kernel(const int* __restrict__ ei) {
    int e = blockIdx.x * blockDim.x + threadIdx.x;
    if (e < EE) atomicAdd(&d_counts[ei[EE + e]], 1);
}

__global__ void scan1_kernel() {
    __shared__ int sh[1024];
    int t = threadIdx.x;
    int idx = blockIdx.x * 1024 + t;
    int v = (idx < NN) ? d_counts[idx] : 0;
    sh[t] = v;
    __syncthreads();
    #pragma unroll
    for (int off = 1; off < 1024; off <<= 1) {
        int tmp = (t >= off) ? sh[t - off] : 0;
        __syncthreads();
        sh[t] += tmp;
        __syncthreads();
    }
    if (idx < NN) d_offs[idx] = sh[t] - v;          // exclusive
    if (t == 1023) d_bsums[blockIdx.x] = sh[1023];  // block total
}

__global__ void scan2_kernel() {
    if (threadIdx.x == 0) {
        int run = 0;
        for (int b = 0; b < NB; b++) { int x = d_bsums[b]; d_bsums[b] = run; run += x; }
    }
}

__global__ void scan3_kernel() {
    int t = threadIdx.x;
    int idx = blockIdx.x * 1024 + t;
    if (idx < NN) {
        int o = d_offs[idx] + d_bsums[blockIdx.x];
        d_offs[idx] = o;
        d_cursor[idx] = o;
    }
}

__global__ void fill_kernel(const int* __restrict__ ei) {
    int e = blockIdx.x * blockDim.x + threadIdx.x;
    if (e < EE) {
        int s = ei[e];
        int d = ei[EE + e];
        int p = atomicAdd(&d_cursor[d], 1);
        d_srcs[p] = s;
    }
}

__global__ void dinv_kernel() {
    int i = blockIdx.x * blockDim.x + threadIdx.x;
    if (i < NN) d_dinv[i] = rsqrtf((float)(d_counts[i] + 1));  // +1 self loop
}

// ---------------- GEMM 1: g1 = dinv * (x @ W1), x:[N,32] W1:[32,64] ----------------
__global__ __launch_bounds__(128) void gemm1_kernel(const float* __restrict__ x,
                                                    const float* __restrict__ W1) {
    __shared__ float Ws[32 * 64];
    for (int t = threadIdx.x; t < 32 * 64; t += 128) Ws[t] = W1[t];
    __syncthreads();
    int i = blockIdx.x * 128 + threadIdx.x;
    if (i >= NN) return;
    float xr[32];
    const float4* xp = reinterpret_cast<const float4*>(x) + i * 8;
    #pragma unroll
    for (int q = 0; q < 8; q++) {
        float4 v = xp[q];
        xr[4*q] = v.x; xr[4*q+1] = v.y; xr[4*q+2] = v.z; xr[4*q+3] = v.w;
    }
    float dv = d_dinv[i];
    #pragma unroll
    for (int h = 0; h < 2; h++) {   // two halves of 32 output cols to cap regs
        float acc[32];
        #pragma unroll
        for (int j = 0; j < 32; j++) acc[j] = 0.f;
        #pragma unroll
        for (int k = 0; k < 32; k++) {
            float xk = xr[k];
            #pragma unroll
            for (int j = 0; j < 32; j++) acc[j] += xk * Ws[k * 64 + h * 32 + j];
        }
        float4* gp = reinterpret_cast<float4*>(d_g1) + i * 16 + h * 8;
        #pragma unroll
        for (int q = 0; q < 8; q++) {
            float4 v;
            v.x = dv * acc[4*q];   v.y = dv * acc[4*q+1];
            v.z = dv * acc[4*q+2]; v.w = dv * acc[4*q+3];
            gp[q] = v;
        }
    }
}

// ---------------- Aggregation 1 (warp per node, 64 feats = float2/lane) ----------------
__global__ __launch_bounds__(256) void agg1_kernel(const float* __restrict__ b1) {
    int warp = threadIdx.x >> 5, lane = threadIdx.x & 31;
    int i = blockIdx.x * 8 + warp;
    if (i >= NN) return;
    const float2* g = reinterpret_cast<const float2*>(d_g1);
    float2 acc = g[i * 32 + lane];   // self-loop term
    int start = d_offs[i], cnt = d_counts[i];
    for (int base = 0; base < cnt; base += 32) {
        int rem = cnt - base;
        int s = (lane < rem) ? d_srcs[start + base + lane] : 0;
        int m = rem < 32 ? rem : 32;
        for (int j = 0; j < m; j++) {
            int sj = __shfl_sync(0xffffffffu, s, j);
            float2 gv = g[sj * 32 + lane];
            acc.x += gv.x; acc.y += gv.y;
        }
    }
    float dv = d_dinv[i];
    float vx = fmaxf(acc.x * dv + __ldg(&b1[2 * lane]), 0.f);
    float vy = fmaxf(acc.y * dv + __ldg(&b1[2 * lane + 1]), 0.f);
    reinterpret_cast<float2*>(d_h1)[i * 32 + lane] = make_float2(vx, vy);
}

// ---------------- GEMM 2: g2 = dinv * (h1 @ W2), h1:[N,64] W2:[64,32] ----------------
__global__ __launch_bounds__(128) void gemm2_kernel(const float* __restrict__ W2) {
    __shared__ float Ws[64 * 32];
    for (int t = threadIdx.x; t < 64 * 32; t += 128) Ws[t] = W2[t];
    __syncthreads();
    int i = blockIdx.x * 128 + threadIdx.x;
    if (i >= NN) return;
    float acc[32];
    #pragma unroll
    for (int j = 0; j < 32; j++) acc[j] = 0.f;
    const float4* hp = reinterpret_cast<const float4*>(d_h1) + i * 16;
    #pragma unroll
    for (int q = 0; q < 16; q++) {
        float4 v = hp[q];
        #pragma unroll
        for (int j = 0; j < 32; j++) {
            acc[j] += v.x * Ws[(4*q)   * 32 + j]
                    + v.y * Ws[(4*q+1) * 32 + j]
                    + v.z * Ws[(4*q+2) * 32 + j]
                    + v.w * Ws[(4*q+3) * 32 + j];
        }
    }
    float dv = d_dinv[i];
    float4* gp = reinterpret_cast<float4*>(d_g2) + i * 8;
    #pragma unroll
    for (int q = 0; q < 8; q++) {
        float4 v;
        v.x = dv * acc[4*q];   v.y = dv * acc[4*q+1];
        v.z = dv * acc[4*q+2]; v.w = dv * acc[4*q+3];
        gp[q] = v;
    }
}

// ---------------- Aggregation 2 (warp per node, 32 feats = 1 float/lane) ----------------
__global__ __launch_bounds__(256) void agg2_kernel(const float* __restrict__ b2,
                                                   float* __restrict__ out) {
    int warp = threadIdx.x >> 5, lane = threadIdx.x & 31;
    int i = blockIdx.x * 8 + warp;
    if (i >= NN) return;
    float acc = d_g2[i * 32 + lane];  // self-loop term
    int start = d_offs[i], cnt = d_counts[i];
    for (int base = 0; base < cnt; base += 32) {
        int rem = cnt - base;
        int s = (lane < rem) ? d_srcs[start + base + lane] : 0;
        int m = rem < 32 ? rem : 32;
        for (int j = 0; j < m; j++) {
            int sj = __shfl_sync(0xffffffffu, s, j);
            acc += d_g2[sj * 32 + lane];
        }
    }
    out[i * 32 + lane] = acc * d_dinv[i] + __ldg(&b2[lane]);
}

// ---------------- launch ----------------
extern "C" void kernel_launch(void* const* d_in, const int* in_sizes, int n_in,
                              void* d_out, int out_size) {
    const float* x  = (const float*)d_in[0];
    const int*   ei = (const int*)  d_in[1];
    const float* W1 = (const float*)d_in[2];
    const float* b1 = (const float*)d_in[3];
    const float* W2 = (const float*)d_in[4];
    const float* b2 = (const float*)d_in[5];
    float* out = (float*)d_out;

    zero_counts_kernel<<<(NN + 255) / 256, 256>>>();
    hist_kernel<<<(EE + 255) / 256, 256>>>(ei);
    scan1_kernel<<<NB, 1024>>>();
    scan2_kernel<<<1, 32>>>();
    scan3_kernel<<<NB, 1024>>>();
    fill_kernel<<<(EE + 255) / 256, 256>>>(ei);
    dinv_kernel<<<(NN + 255) / 256, 256>>>();

    gemm1_kernel<<<(NN + 127) / 128, 128>>>(x, W1);
    agg1_kernel<<<(NN + 7) / 8, 256>>>(b1);
    gemm2_kernel<<<(NN + 127) / 128, 128>>>(W2);
    agg2_kernel<<<(NN + 7) / 8, 256>>>(b2, out);
}

// round 2
// speedup vs baseline: 1.2079x; 1.2079x over previous
#include <cuda_runtime.h>

#define NN 100000
#define EE 1600000
#define NB 98   /* ceil(NN/1024) */

// ---------------- device scratch ----------------
__device__ int   d_counts[NN];     // in-degree (w/o self loop)
__device__ int   d_offs[NN];       // CSR-T row starts
__device__ int   d_cursor[NN];     // fill cursors
__device__ int   d_bsums[NB];      // scan block sums
__device__ int   d_srcs[EE];       // CSR-T column indices
__device__ float d_dinv[NN];       // rsqrt(deg)
__device__ float d_g0[NN * 32];    // dinv * x
__device__ float d_a0[NN * 32];    // layer-1 aggregated input
__device__ float d_g2[NN * 32];    // dinv * (relu(a0@W1+b1) @ W2)

// ---------------- CSR build ----------------
__global__ void zero_counts_kernel() {
    int i = blockIdx.x * blockDim.x + threadIdx.x;
    if (i < NN) d_counts[i] = 0;
}

__global__ void hist_kernel(const int* __restrict__ ei) {
    int e = blockIdx.x * blockDim.x + threadIdx.x;
    if (e < EE) atomicAdd(&d_counts[ei[EE + e]], 1);
}

__global__ void scan1_kernel() {
    __shared__ int sh[1024];
    int t = threadIdx.x;
    int idx = blockIdx.x * 1024 + t;
    int v = (idx < NN) ? d_counts[idx] : 0;
    sh[t] = v;
    __syncthreads();
    #pragma unroll
    for (int off = 1; off < 1024; off <<= 1) {
        int tmp = (t >= off) ? sh[t - off] : 0;
        __syncthreads();
        sh[t] += tmp;
        __syncthreads();
    }
    if (idx < NN) d_offs[idx] = sh[t] - v;          // exclusive within block
    if (t == 1023) d_bsums[blockIdx.x] = sh[1023];  // block total
}

// scan3: each block computes its own prefix base from d_bsums (98 values)
__global__ void scan3_kernel() {
    __shared__ int wsum[32];
    __shared__ int base_sh;
    int t = threadIdx.x;
    int b = blockIdx.x;
    int v = (t < b) ? d_bsums[t] : 0;   // t < 1024 >= NB
    #pragma unroll
    for (int o = 16; o > 0; o >>= 1) v += __shfl_down_sync(0xffffffffu, v, o);
    if ((t & 31) == 0) wsum[t >> 5] = v;
    __syncthreads();
    if (t < 32) {
        int w = wsum[t];
        #pragma unroll
        for (int o = 16; o > 0; o >>= 1) w += __shfl_down_sync(0xffffffffu, w, o);
        if (t == 0) base_sh = w;
    }
    __syncthreads();
    int idx = b * 1024 + t;
    if (idx < NN) {
        int o = d_offs[idx] + base_sh;
        d_offs[idx] = o;
        d_cursor[idx] = o;
    }
}

__global__ void fill_kernel(const int* __restrict__ ei) {
    int e = blockIdx.x * blockDim.x + threadIdx.x;
    if (e < EE) {
        int s = ei[e];
        int d = ei[EE + e];
        int p = atomicAdd(&d_cursor[d], 1);
        d_srcs[p] = s;
    }
}

// ---------------- prep: dinv = rsqrt(deg), g0 = dinv * x ----------------
// thread t handles float4 chunk c of node i (8 chunks per node)
__global__ void prep_kernel(const float* __restrict__ x) {
    long long t = (long long)blockIdx.x * blockDim.x + threadIdx.x;
    if (t >= (long long)NN * 8) return;
    int i = (int)(t >> 3);
    int c = (int)(t & 7);
    float dv = rsqrtf((float)(d_counts[i] + 1));
    if (c == 0) d_dinv[i] = dv;
    float4 v = reinterpret_cast<const float4*>(x)[t];
    v.x *= dv; v.y *= dv; v.z *= dv; v.w *= dv;
    reinterpret_cast<float4*>(d_g0)[t] = v;
}

// ---------------- 32-dim aggregation: out[d] = dinv[d]*(sum_{s->d} g[s] + g[d]) ----------------
template<bool RELU_BIAS>
__device__ __forceinline__ void agg32(const float* __restrict__ g,
                                      float* __restrict__ outp,
                                      const float* __restrict__ bias) {
    int warp = threadIdx.x >> 5, lane = threadIdx.x & 31;
    int i = blockIdx.x * 8 + warp;
    if (i >= NN) return;
    float acc = g[i * 32 + lane];   // self-loop term
    int start = d_offs[i], cnt = d_counts[i];
    int base = 0;
    for (; base + 32 <= cnt; base += 32) {
        int s = d_srcs[start + base + lane];
        #pragma unroll
        for (int j = 0; j < 32; j++) {
            int sj = __shfl_sync(0xffffffffu, s, j);
            acc += g[sj * 32 + lane];
        }
    }
    int rem = cnt - base;
    if (rem > 0) {
        int s = (lane < rem) ? d_srcs[start + base + lane] : 0;
        for (int j = 0; j < rem; j++) {
            int sj = __shfl_sync(0xffffffffu, s, j);
            acc += g[sj * 32 + lane];
        }
    }
    float v = acc * d_dinv[i];
    if (RELU_BIAS) v = fmaxf(v + bias[lane], 0.f);
    else if (bias) v += bias[lane];
    outp[i * 32 + lane] = v;
}

__global__ __launch_bounds__(256) void agg0_kernel() {
    agg32<false>(d_g0, d_a0, nullptr);
}

__global__ __launch_bounds__(256) void agg2_kernel(const float* __restrict__ b2,
                                                   float* __restrict__ out) {
    agg32<false>(d_g2, out, b2);
}

// ---------------- fused MLP: g2 = dinv * (relu(a0@W1 + b1) @ W2) ----------------
__global__ __launch_bounds__(128) void mlp_kernel(const float* __restrict__ W1,
                                                  const float* __restrict__ b1,
                                                  const float* __restrict__ W2) {
    __shared__ float W1s[32 * 64];
    __shared__ float W2s[64 * 32];
    __shared__ float b1s[64];
    for (int t = threadIdx.x; t < 32 * 64; t += 128) W1s[t] = W1[t];
    for (int t = threadIdx.x; t < 64 * 32; t += 128) W2s[t] = W2[t];
    if (threadIdx.x < 64) b1s[threadIdx.x] = b1[threadIdx.x];
    __syncthreads();
    int i = blockIdx.x * 128 + threadIdx.x;
    if (i >= NN) return;

    float a[32];
    const float4* ap = reinterpret_cast<const float4*>(d_a0) + i * 8;
    #pragma unroll
    for (int q = 0; q < 8; q++) {
        float4 v = ap[q];
        a[4*q] = v.x; a[4*q+1] = v.y; a[4*q+2] = v.z; a[4*q+3] = v.w;
    }

    float acc[32];
    #pragma unroll
    for (int j = 0; j < 32; j++) acc[j] = 0.f;

    #pragma unroll
    for (int half = 0; half < 2; half++) {
        float h[32];
        #pragma unroll
        for (int jj = 0; jj < 32; jj++) h[jj] = b1s[half * 32 + jj];
        #pragma unroll
        for (int k = 0; k < 32; k++) {
            float ak = a[k];
            #pragma unroll
            for (int jj = 0; jj < 32; jj++)
                h[jj] += ak * W1s[k * 64 + half * 32 + jj];
        }
        #pragma unroll
        for (int jj = 0; jj < 32; jj++) {
            float hv = fmaxf(h[jj], 0.f);
            #pragma unroll
            for (int j = 0; j < 32; j++)
                acc[j] += hv * W2s[(half * 32 + jj) * 32 + j];
        }
    }

    float dv = d_dinv[i];
    float4* gp = reinterpret_cast<float4*>(d_g2) + i * 8;
    #pragma unroll
    for (int q = 0; q < 8; q++) {
        float4 v;
        v.x = dv * acc[4*q];   v.y = dv * acc[4*q+1];
        v.z = dv * acc[4*q+2]; v.w = dv * acc[4*q+3];
        gp[q] = v;
    }
}

// ---------------- launch ----------------
extern "C" void kernel_launch(void* const* d_in, const int* in_sizes, int n_in,
                              void* d_out, int out_size) {
    const float* x  = (const float*)d_in[0];
    const int*   ei = (const int*)  d_in[1];
    const float* W1 = (const float*)d_in[2];
    const float* b1 = (const float*)d_in[3];
    const float* W2 = (const float*)d_in[4];
    const float* b2 = (const float*)d_in[5];
    float* out = (float*)d_out;

    zero_counts_kernel<<<(NN + 255) / 256, 256>>>();
    hist_kernel<<<(EE + 255) / 256, 256>>>(ei);
    prep_kernel<<<(NN * 8 + 255) / 256, 256>>>(x);   // needs counts only
    scan1_kernel<<<NB, 1024>>>();
    scan3_kernel<<<NB, 1024>>>();
    fill_kernel<<<(EE + 255) / 256, 256>>>(ei);

    agg0_kernel<<<(NN + 7) / 8, 256>>>();
    mlp_kernel<<<(NN + 127) / 128, 128>>>(W1, b1, W2);
    agg2_kernel<<<(NN + 7) / 8, 256>>>(b2, out);
}

// round 3
// speedup vs baseline: 1.3002x; 1.0764x over previous
#include <cuda_runtime.h>
#include <cuda_fp16.h>

#define NN 100000
#define EE 1600000
#define NB 98   /* ceil(NN/1024) */

typedef unsigned long long u64;

// ---------------- device scratch ----------------
__device__ int    d_counts[NN];
__device__ int    d_offs[NN];
__device__ int    d_cursor[NN];
__device__ int    d_bsums[NB];
__device__ int    d_srcs[EE];
__device__ float  d_dinv[NN];
__device__ __half d_g0h[NN * 32];   // half(dinv * x)
__device__ float  d_a0[NN * 32];    // layer-1 aggregated input (fp32)
__device__ __half d_g2h[NN * 32];   // half(dinv * mlp(a0))

// ---------------- f32x2 helpers ----------------
__device__ __forceinline__ u64 pack2(float lo, float hi) {
    u64 r; asm("mov.b64 %0, {%1, %2};" : "=l"(r) : "f"(lo), "f"(hi)); return r;
}
__device__ __forceinline__ u64 fma2(u64 a, u64 b, u64 c) {
    u64 d; asm("fma.rn.f32x2 %0, %1, %2, %3;" : "=l"(d) : "l"(a), "l"(b), "l"(c)); return d;
}
__device__ __forceinline__ float2 unpack2(u64 v) {
    float2 f; asm("mov.b64 {%0, %1}, %2;" : "=f"(f.x), "=f"(f.y) : "l"(v)); return f;
}

// ---------------- CSR build ----------------
__global__ void zero_counts_kernel() {
    int i = blockIdx.x * blockDim.x + threadIdx.x;
    if (i < NN) d_counts[i] = 0;
}

__global__ void hist_kernel(const int* __restrict__ ei) {
    int t = blockIdx.x * blockDim.x + threadIdx.x;
    if (t >= EE / 4) return;
    int4 d = reinterpret_cast<const int4*>(ei + EE)[t];
    atomicAdd(&d_counts[d.x], 1);
    atomicAdd(&d_counts[d.y], 1);
    atomicAdd(&d_counts[d.z], 1);
    atomicAdd(&d_counts[d.w], 1);
}

// 256 threads x 4 elems = 1024 per block, warp-shuffle scan
__global__ __launch_bounds__(256) void scan1_kernel() {
    __shared__ int wsums[8];
    int t = threadIdx.x, b = blockIdx.x;
    int lane = t & 31, warp = t >> 5;
    int base = b * 1024 + t * 4;
    int4 c = make_int4(0, 0, 0, 0);
    if (base + 3 < NN) c = *reinterpret_cast<const int4*>(&d_counts[base]);
    else {
        if (base     < NN) c.x = d_counts[base];
        if (base + 1 < NN) c.y = d_counts[base + 1];
        if (base + 2 < NN) c.z = d_counts[base + 2];
        if (base + 3 < NN) c.w = d_counts[base + 3];
    }
    int s = c.x + c.y + c.z + c.w;
    int incl = s;
    #pragma unroll
    for (int o = 1; o < 32; o <<= 1) {
        int v = __shfl_up_sync(0xffffffffu, incl, o);
        if (lane >= o) incl += v;
    }
    if (lane == 31) wsums[warp] = incl;
    __syncthreads();
    if (t < 8) {
        int v = wsums[t];
        int p = v;
        #pragma unroll
        for (int o = 1; o < 8; o <<= 1) {
            int u = __shfl_up_sync(0xffu, p, o);
            if (t >= o) p += u;
        }
        wsums[t] = p - v;               // exclusive warp base
        if (t == 7) d_bsums[b] = p;     // block total
    }
    __syncthreads();
    int excl = incl - s + wsums[warp];
    int p0 = excl, p1 = p0 + c.x, p2 = p1 + c.y, p3 = p2 + c.z;
    if (base + 3 < NN) {
        *reinterpret_cast<int4*>(&d_offs[base]) = make_int4(p0, p1, p2, p3);
    } else {
        if (base     < NN) d_offs[base]     = p0;
        if (base + 1 < NN) d_offs[base + 1] = p1;
        if (base + 2 < NN) d_offs[base + 2] = p2;
        if (base + 3 < NN) d_offs[base + 3] = p3;
    }
}

// add cross-block base (reduce bsums[0..b)) and init cursor
__global__ void scan3_kernel() {
    __shared__ int wsum[32];
    __shared__ int base_sh;
    int t = threadIdx.x, b = blockIdx.x;
    int v = (t < b) ? d_bsums[t] : 0;
    #pragma unroll
    for (int o = 16; o > 0; o >>= 1) v += __shfl_down_sync(0xffffffffu, v, o);
    if ((t & 31) == 0) wsum[t >> 5] = v;
    __syncthreads();
    if (t < 32) {
        int w = wsum[t];
        #pragma unroll
        for (int o = 16; o > 0; o >>= 1) w += __shfl_down_sync(0xffffffffu, w, o);
        if (t == 0) base_sh = w;
    }
    __syncthreads();
    int idx = b * 1024 + t;
    if (idx < NN) {
        int o = d_offs[idx] + base_sh;
        d_offs[idx] = o;
        d_cursor[idx] = o;
    }
}

__global__ void fill_kernel(const int* __restrict__ ei) {
    int t = blockIdx.x * blockDim.x + threadIdx.x;
    if (t >= EE / 4) return;
    int4 s = reinterpret_cast<const int4*>(ei)[t];
    int4 d = reinterpret_cast<const int4*>(ei + EE)[t];
    d_srcs[atomicAdd(&d_cursor[d.x], 1)] = s.x;
    d_srcs[atomicAdd(&d_cursor[d.y], 1)] = s.y;
    d_srcs[atomicAdd(&d_cursor[d.z], 1)] = s.z;
    d_srcs[atomicAdd(&d_cursor[d.w], 1)] = s.w;
}

// ---------------- prep: dinv = rsqrt(deg), g0h = half(dinv * x) ----------------
__global__ void prep_kernel(const float* __restrict__ x) {
    int t = blockIdx.x * blockDim.x + threadIdx.x;
    if (t >= NN * 8) return;
    int i = t >> 3;
    float dv = rsqrtf((float)(d_counts[i] + 1));
    if ((t & 7) == 0) d_dinv[i] = dv;
    float4 v = reinterpret_cast<const float4*>(x)[t];
    __half2 h01 = __floats2half2_rn(v.x * dv, v.y * dv);
    __half2 h23 = __floats2half2_rn(v.z * dv, v.w * dv);
    uint2 u;
    u.x = *reinterpret_cast<unsigned*>(&h01);
    u.y = *reinterpret_cast<unsigned*>(&h23);
    reinterpret_cast<uint2*>(d_g0h)[t] = u;
}

// ---------------- 32-dim aggregation over half payload ----------------
__device__ __forceinline__ float agg32h(const __half* __restrict__ g, int i, int lane) {
    float acc = __half2float(g[i * 32 + lane]);   // self loop
    int start = d_offs[i], cnt = d_counts[i];
    int base = 0;
    for (; base + 32 <= cnt; base += 32) {
        int s = d_srcs[start + base + lane];
        #pragma unroll
        for (int j = 0; j < 32; j++) {
            int sj = __shfl_sync(0xffffffffu, s, j);
            acc += __half2float(g[sj * 32 + lane]);
        }
    }
    int rem = cnt - base;
    if (rem > 0) {
        int s = (lane < rem) ? d_srcs[start + base + lane] : 0;
        for (int j = 0; j < rem; j++) {
            int sj = __shfl_sync(0xffffffffu, s, j);
            acc += __half2float(g[sj * 32 + lane]);
        }
    }
    return acc;
}

__global__ __launch_bounds__(256) void agg0_kernel() {
    int warp = threadIdx.x >> 5, lane = threadIdx.x & 31;
    int i = blockIdx.x * 8 + warp;
    if (i >= NN) return;
    float acc = agg32h(d_g0h, i, lane);
    d_a0[i * 32 + lane] = acc * d_dinv[i];
}

__global__ __launch_bounds__(256) void agg2_kernel(const float* __restrict__ b2,
                                                   float* __restrict__ out) {
    int warp = threadIdx.x >> 5, lane = threadIdx.x & 31;
    int i = blockIdx.x * 8 + warp;
    if (i >= NN) return;
    float acc = agg32h(d_g2h, i, lane);
    out[i * 32 + lane] = acc * d_dinv[i] + __ldg(&b2[lane]);
}

// ---------------- fused MLP with f32x2: g2h = half(dinv * (relu(a0@W1+b1) @ W2)) ----------------
__global__ __launch_bounds__(128) void mlp_kernel(const float* __restrict__ W1,
                                                  const float* __restrict__ b1,
                                                  const float* __restrict__ W2) {
    __shared__ float W1s[32 * 64];   // [k][64] row-major -> pairs contiguous
    __shared__ float W2s[64 * 32];   // [jj][32]
    __shared__ float b1s[64];
    for (int t = threadIdx.x; t < 32 * 64; t += 128) W1s[t] = W1[t];
    for (int t = threadIdx.x; t < 64 * 32; t += 128) W2s[t] = W2[t];
    if (threadIdx.x < 64) b1s[threadIdx.x] = b1[threadIdx.x];
    __syncthreads();
    const u64* W1p = reinterpret_cast<const u64*>(W1s);   // [k][32 pairs]
    const u64* W2p = reinterpret_cast<const u64*>(W2s);   // [jj][16 pairs]

    int i = blockIdx.x * 128 + threadIdx.x;
    if (i >= NN) return;

    float a[32];
    const float4* ap = reinterpret_cast<const float4*>(d_a0) + i * 8;
    #pragma unroll
    for (int q = 0; q < 8; q++) {
        float4 v = ap[q];
        a[4*q] = v.x; a[4*q+1] = v.y; a[4*q+2] = v.z; a[4*q+3] = v.w;
    }

    // layer 1: h[64] as 32 packed pairs
    u64 h2[32];
    #pragma unroll
    for (int j = 0; j < 32; j++) h2[j] = pack2(b1s[2*j], b1s[2*j+1]);
    #pragma unroll
    for (int k = 0; k < 32; k++) {
        u64 ak = pack2(a[k], a[k]);
        #pragma unroll
        for (int j = 0; j < 32; j++)
            h2[j] = fma2(ak, W1p[k * 32 + j], h2[j]);
    }

    // relu + layer 2: acc[32] as 16 packed pairs
    u64 acc2[16];
    #pragma unroll
    for (int j = 0; j < 16; j++) acc2[j] = pack2(0.f, 0.f);
    #pragma unroll
    for (int jj = 0; jj < 32; jj++) {
        float2 hp = unpack2(h2[jj]);
        float h0 = fmaxf(hp.x, 0.f), h1 = fmaxf(hp.y, 0.f);
        u64 h0d = pack2(h0, h0), h1d = pack2(h1, h1);
        #pragma unroll
        for (int j = 0; j < 16; j++) acc2[j] = fma2(h0d, W2p[(2*jj)   * 16 + j], acc2[j]);
        #pragma unroll
        for (int j = 0; j < 16; j++) acc2[j] = fma2(h1d, W2p[(2*jj+1) * 16 + j], acc2[j]);
    }

    float dv = d_dinv[i];
    unsigned ou[16];
    #pragma unroll
    for (int j = 0; j < 16; j++) {
        float2 v = unpack2(acc2[j]);
        __half2 hh = __floats2half2_rn(v.x * dv, v.y * dv);
        ou[j] = *reinterpret_cast<unsigned*>(&hh);
    }
    uint4* gp = reinterpret_cast<uint4*>(d_g2h) + i * 4;
    #pragma unroll
    for (int q = 0; q < 4; q++)
        gp[q] = make_uint4(ou[4*q], ou[4*q+1], ou[4*q+2], ou[4*q+3]);
}

// ---------------- launch ----------------
extern "C" void kernel_launch(void* const* d_in, const int* in_sizes, int n_in,
                              void* d_out, int out_size) {
    const float* x  = (const float*)d_in[0];
    const int*   ei = (const int*)  d_in[1];
    const float* W1 = (const float*)d_in[2];
    const float* b1 = (const float*)d_in[3];
    const float* W2 = (const float*)d_in[4];
    const float* b2 = (const float*)d_in[5];
    float* out = (float*)d_out;

    zero_counts_kernel<<<(NN + 255) / 256, 256>>>();
    hist_kernel<<<(EE / 4 + 255) / 256, 256>>>(ei);
    prep_kernel<<<(NN * 8 + 255) / 256, 256>>>(x);
    scan1_kernel<<<NB, 256>>>();
    scan3_kernel<<<NB, 1024>>>();
    fill_kernel<<<(EE / 4 + 255) / 256, 256>>>(ei);

    agg0_kernel<<<(NN + 7) / 8, 256>>>();
    mlp_kernel<<<(NN + 127) / 128, 128>>>(W1, b1, W2);
    agg2_kernel<<<(NN + 7) / 8, 256>>>(b2, out);
}